// round 1
// baseline (speedup 1.0000x reference)
#include <cuda_runtime.h>
#include <cuda_bf16.h>
#include <math.h>

// ---------------- problem constants (fixed shapes) ----------------
#define NN      65536          // nodes
#define NB      128            // graphs
#define NG      512            // nodes/graph
#define NE      65536          // directed edges before flip+loops
#define ETOT    (2*NE + NN)    // 196608
#define IN_F    512
#define HID     64
#define OUTF    64
#define NHEAD   4
#define NC      4

// ---------------- scratch (device globals; no allocation) ----------------
__device__ float g_rc1[NB*HID];
__device__ float g_rc2[NB*HID];
__device__ float g_hx [(size_t)NN*HID];
__device__ float g_h1 [(size_t)NN*2*HID];
__device__ float g_hlin1[(size_t)NN*256];
__device__ float g_out1 [(size_t)NN*256];
__device__ float g_x2r  [(size_t)NN*256];
__device__ float g_hs   [(size_t)NN*256];
__device__ float g_x3   [(size_t)NN*512];
__device__ float g_hlin2[(size_t)NN*256];
__device__ float g_out2 [(size_t)NN*256];
__device__ float g_xr2  [(size_t)NN*64];
__device__ float g_asrc [(size_t)NN*4];
__device__ float g_adst [(size_t)NN*4];
__device__ unsigned g_maxu[(size_t)NN*4];
__device__ float g_den  [(size_t)NN*4];
__device__ float g_ebuf [(size_t)ETOT*4];
__device__ float g_shat [NB*64];
__device__ float g_ssum [NB*64];

// ---------------- generic register-blocked SGEMM ----------------
// C[M,N] = A[M,K] @ B[K,N].  BM=128, BN=64, BK=32, 256 threads, 8x4 microtile.
// Requires M%128==0, N%64==0, K%32==0 (all our shapes satisfy this).
__global__ __launch_bounds__(256) void sgemm128(
    const float* __restrict__ A, const float* __restrict__ B,
    float* __restrict__ C, int M, int N, int K)
{
    __shared__ float As[32][128+4];
    __shared__ float Bs[32][64];
    const int tid = threadIdx.x;
    const int tx = tid & 15;        // 0..15 -> 4 cols each
    const int ty = tid >> 4;        // 0..15 -> 8 rows each
    const int m0 = blockIdx.y * 128;
    const int n0 = blockIdx.x * 64;
    float acc[8][4];
    #pragma unroll
    for (int i = 0; i < 8; i++)
        #pragma unroll
        for (int j = 0; j < 4; j++) acc[i][j] = 0.f;

    for (int k0 = 0; k0 < K; k0 += 32) {
        // A tile: 128x32 = 1024 float4, 4 per thread (stored transposed)
        #pragma unroll
        for (int t = 0; t < 4; t++) {
            int idx = tid + t*256;
            int r = idx >> 3, c4 = (idx & 7) << 2;
            float4 v = *(const float4*)(A + (size_t)(m0 + r)*K + k0 + c4);
            As[c4+0][r] = v.x; As[c4+1][r] = v.y;
            As[c4+2][r] = v.z; As[c4+3][r] = v.w;
        }
        // B tile: 32x64 = 512 float4, 2 per thread
        #pragma unroll
        for (int t = 0; t < 2; t++) {
            int idx = tid + t*256;
            int r = idx >> 4, c4 = (idx & 15) << 2;
            *(float4*)(&Bs[r][c4]) = *(const float4*)(B + (size_t)(k0 + r)*N + n0 + c4);
        }
        __syncthreads();
        #pragma unroll
        for (int k = 0; k < 32; k++) {
            float4 a0 = *(const float4*)(&As[k][ty*8]);
            float4 a1 = *(const float4*)(&As[k][ty*8+4]);
            float4 b  = *(const float4*)(&Bs[k][tx*4]);
            float av[8] = {a0.x,a0.y,a0.z,a0.w,a1.x,a1.y,a1.z,a1.w};
            float bv[4] = {b.x,b.y,b.z,b.w};
            #pragma unroll
            for (int i = 0; i < 8; i++)
                #pragma unroll
                for (int j = 0; j < 4; j++) acc[i][j] += av[i]*bv[j];
        }
        __syncthreads();
    }
    #pragma unroll
    for (int i = 0; i < 8; i++) {
        float4 v = make_float4(acc[i][0], acc[i][1], acc[i][2], acc[i][3]);
        *(float4*)(C + (size_t)(m0 + ty*8 + i)*N + n0 + tx*4) = v;
    }
}

// ---------------- elementwise / fusion kernels ----------------
__global__ void e1_gate(const int* __restrict__ batch) {
    size_t idx = (size_t)blockIdx.x*blockDim.x + threadIdx.x;
    if (idx >= (size_t)NN*HID) return;
    int n = (int)(idx >> 6), c = (int)(idx & 63);
    float hx = g_hx[idx];
    float hc = g_rc1[batch[n]*HID + c];
    float g = 1.f / (1.f + expf(-(hx + hc)));
    g_h1[(size_t)n*128 + c]      = g*hx + (1.f - g)*hc;
    g_h1[(size_t)n*128 + 64 + c] = hx;
}

__global__ void e3_relu_bias(const float* __restrict__ b1) {
    size_t idx = (size_t)blockIdx.x*blockDim.x + threadIdx.x;
    if (idx >= (size_t)NN*256) return;
    float v = g_out1[idx] + b1[idx & 255];
    g_x2r[idx] = v > 0.f ? v : 0.f;
}

__global__ void e4_gate2(const int* __restrict__ batch) {
    size_t idx = (size_t)blockIdx.x*blockDim.x + threadIdx.x;
    if (idx >= (size_t)NN*256) return;
    int n = (int)(idx >> 8), r = (int)(idx & 255);
    int k = r >> 6, c = r & 63;
    float hs = g_hs[idx];
    float hc = g_rc2[batch[n]*HID + c];
    float g = 1.f / (1.f + expf(-(hs + hc)));
    g_x3[(size_t)n*512 + k*128 + c]      = g*hs + (1.f - g)*hc;
    g_x3[(size_t)n*512 + k*128 + 64 + c] = hs;
}

__global__ void e6_headmean(const float* __restrict__ b2) {
    size_t idx = (size_t)blockIdx.x*blockDim.x + threadIdx.x;
    if (idx >= (size_t)NN*64) return;
    int n = (int)(idx >> 6), c = (int)(idx & 63);
    size_t base = (size_t)n*256;
    float s = (g_out2[base+c] + g_out2[base+64+c] + g_out2[base+128+c] + g_out2[base+192+c])*0.25f
              + b2[c];
    g_xr2[idx] = s > 0.f ? s : 0.f;
}

// ---------------- attention score reduction: warp per node ----------------
__global__ void attn_scores(const float* __restrict__ h,
                            const float* __restrict__ aw_src,
                            const float* __restrict__ aw_dst) {
    int w = (int)(((size_t)blockIdx.x*blockDim.x + threadIdx.x) >> 5);
    int lane = threadIdx.x & 31;
    if (w >= NN) return;
    const float* row = h + (size_t)w*256;
    #pragma unroll
    for (int hh = 0; hh < 4; hh++) {
        float v0 = row[hh*64 + lane], v1 = row[hh*64 + 32 + lane];
        float sa = v0*aw_src[hh*64+lane] + v1*aw_src[hh*64+32+lane];
        float sd = v0*aw_dst[hh*64+lane] + v1*aw_dst[hh*64+32+lane];
        #pragma unroll
        for (int off = 16; off; off >>= 1) {
            sa += __shfl_down_sync(0xffffffffu, sa, off);
            sd += __shfl_down_sync(0xffffffffu, sd, off);
        }
        if (lane == 0) { g_asrc[w*4+hh] = sa; g_adst[w*4+hh] = sd; }
    }
}

// ---------------- edge helpers ----------------
__device__ __forceinline__ void edge_sd(const int* __restrict__ ei, int i, int& s, int& d) {
    if (i < NE)            { s = ei[i];            d = ei[NE + i]; }
    else if (i < 2*NE)     { int j = i - NE; s = ei[NE + j]; d = ei[j]; }
    else                   { s = d = i - 2*NE; }
}
__device__ __forceinline__ unsigned fenc(float f) {
    unsigned b = __float_as_uint(f);
    return (b & 0x80000000u) ? ~b : (b | 0x80000000u);
}
__device__ __forceinline__ float fdec(unsigned u) {
    return (u & 0x80000000u) ? __uint_as_float(u & 0x7FFFFFFFu) : __uint_as_float(~u);
}

__global__ void edge_max(const int* __restrict__ ei) {
    int i = blockIdx.x*blockDim.x + threadIdx.x;
    if (i >= ETOT) return;
    int s, d; edge_sd(ei, i, s, d);
    #pragma unroll
    for (int hh = 0; hh < 4; hh++) {
        float t = g_asrc[s*4+hh] + g_adst[d*4+hh];
        t = t > 0.f ? t : 0.2f*t;                   // LeakyReLU(0.2)
        g_ebuf[(size_t)i*4+hh] = t;
        atomicMax(&g_maxu[d*4+hh], fenc(t));
    }
}

__global__ void edge_den(const int* __restrict__ ei) {
    int i = blockIdx.x*blockDim.x + threadIdx.x;
    if (i >= ETOT) return;
    int s, d; edge_sd(ei, i, s, d); (void)s;
    #pragma unroll
    for (int hh = 0; hh < 4; hh++) {
        float m = fdec(g_maxu[d*4+hh]);
        float ex = expf(g_ebuf[(size_t)i*4+hh] - m);
        g_ebuf[(size_t)i*4+hh] = ex;
        atomicAdd(&g_den[d*4+hh], ex);
    }
}

// warp per edge: out[d, :256] += alpha[head] * h[s, :256]
__global__ void edge_scatter(const int* __restrict__ ei,
                             const float* __restrict__ h, float* __restrict__ out) {
    int w = (int)(((size_t)blockIdx.x*blockDim.x + threadIdx.x) >> 5);
    int lane = threadIdx.x & 31;
    if (w >= ETOT) return;
    int s, d; edge_sd(ei, w, s, d);
    float al[4];
    #pragma unroll
    for (int hh = 0; hh < 4; hh++)
        al[hh] = g_ebuf[(size_t)w*4+hh] / g_den[d*4+hh];
    const float* hr = h + (size_t)s*256;
    float* orow = out + (size_t)d*256;
    #pragma unroll
    for (int t = 0; t < 8; t++) {
        int c = t*32 + lane;
        atomicAdd(&orow[c], al[t >> 1] * hr[c]);
    }
}

// ---------------- pooling: beta = softmax(tanh(h_joint @ W_fc + b_fc)) ----------------
// 256 threads = 4 groups of 64 (one node each); W_fc resident in smem.
__global__ void f1_pool(const float* __restrict__ batch_f_unused,
                        const int* __restrict__ batch,
                        const int* __restrict__ ptr,
                        const float* __restrict__ Wfc,
                        const float* __restrict__ bfc) {
    extern __shared__ float sm[];
    float* sw = sm;               // 256*64
    float* sx = sm + 16384;       // 4*64
    float* sc = sm + 16640;       // 4*64
    float* tb = sm + 16896;       // 4*64
    int tid = threadIdx.x;
    for (int i = tid; i < 16384; i += 256) sw[i] = Wfc[i];
    __syncthreads();
    int grp = tid >> 6, j = tid & 63;
    float bj = bfc[j];
    for (int base = blockIdx.x*4; base < NN; base += gridDim.x*4) {
        int n = base + grp;
        int g = batch[n];
        int rn = ptr[g];
        sx[grp*64 + j] = g_xr2[(size_t)n*64 + j];
        sc[grp*64 + j] = g_xr2[(size_t)rn*64 + j];
        __syncthreads();
        const float* px = sx + grp*64;
        const float* pc = sc + grp*64;
        float t = bj;
        #pragma unroll 8
        for (int i = 0; i < 64; i++) {
            float xv = px[i], cv = pc[i];
            t += cv*sw[i*64 + j] + xv*sw[(64+i)*64 + j]
               + (xv*cv)*sw[(128+i)*64 + j] + fabsf(cv - xv)*sw[(192+i)*64 + j];
        }
        t = tanhf(t);
        tb[tid] = t;
        __syncthreads();
        float mx = -1e30f;
        #pragma unroll 8
        for (int i = 0; i < 64; i++) mx = fmaxf(mx, tb[grp*64 + i]);
        float ex = expf(t - mx);
        __syncthreads();
        tb[tid] = ex;
        __syncthreads();
        float sum = 0.f;
        #pragma unroll 8
        for (int i = 0; i < 64; i++) sum += tb[grp*64 + i];
        float beta = ex / sum;
        float xv = px[j];
        atomicAdd(&g_shat[g*64 + j], beta * xv);
        atomicAdd(&g_ssum[g*64 + j], xv);
        __syncthreads();
    }
}

// ---------------- classifier + log_softmax ----------------
__global__ void f2_clf(const float* __restrict__ Wclf, const float* __restrict__ bclf,
                       float* __restrict__ out) {
    int g = threadIdx.x;   // 128 graphs
    float l[4];
    #pragma unroll
    for (int c = 0; c < 4; c++) l[c] = bclf[c];
    const float inv = 1.0f / (float)NG;
    for (int j = 0; j < 64; j++) {
        float a = g_shat[g*64 + j] * inv;
        float b = g_ssum[g*64 + j] * inv;
        #pragma unroll
        for (int c = 0; c < 4; c++)
            l[c] += a*Wclf[j*4 + c] + b*Wclf[(64+j)*4 + c];
    }
    float m = fmaxf(fmaxf(l[0], l[1]), fmaxf(l[2], l[3]));
    float s = 0.f;
    #pragma unroll
    for (int c = 0; c < 4; c++) s += expf(l[c] - m);
    float ls = logf(s);
    #pragma unroll
    for (int c = 0; c < 4; c++) out[g*4 + c] = l[c] - m - ls;
}

// ---------------- launch ----------------
extern "C" void kernel_launch(void* const* d_in, const int* in_sizes, int n_in,
                              void* d_out, int out_size) {
    const float* x        = (const float*)d_in[0];
    const float* root     = (const float*)d_in[1];
    const int*   ei       = (const int*)  d_in[2];
    const int*   batch    = (const int*)  d_in[3];
    const int*   ptr      = (const int*)  d_in[4];
    const float* W_post1  = (const float*)d_in[5];
    const float* W_claim1 = (const float*)d_in[6];
    const float* W1       = (const float*)d_in[7];
    const float* att_src1 = (const float*)d_in[8];
    const float* att_dst1 = (const float*)d_in[9];
    const float* b1       = (const float*)d_in[10];
    const float* W_post2  = (const float*)d_in[11];
    const float* W_claim2 = (const float*)d_in[12];
    const float* W2       = (const float*)d_in[13];
    const float* att_src2 = (const float*)d_in[14];
    const float* att_dst2 = (const float*)d_in[15];
    const float* b2       = (const float*)d_in[16];
    const float* W_fc     = (const float*)d_in[17];
    const float* b_fc     = (const float*)d_in[18];
    const float* W_clf    = (const float*)d_in[19];
    const float* b_clf    = (const float*)d_in[20];
    float* out = (float*)d_out;

    void *p_rc1, *p_rc2, *p_hx, *p_h1, *p_hlin1, *p_out1, *p_x2r, *p_hs, *p_x3,
         *p_hlin2, *p_out2, *p_xr2, *p_maxu, *p_den, *p_shat, *p_ssum;
    cudaGetSymbolAddress(&p_rc1,   g_rc1);
    cudaGetSymbolAddress(&p_rc2,   g_rc2);
    cudaGetSymbolAddress(&p_hx,    g_hx);
    cudaGetSymbolAddress(&p_h1,    g_h1);
    cudaGetSymbolAddress(&p_hlin1, g_hlin1);
    cudaGetSymbolAddress(&p_out1,  g_out1);
    cudaGetSymbolAddress(&p_x2r,   g_x2r);
    cudaGetSymbolAddress(&p_hs,    g_hs);
    cudaGetSymbolAddress(&p_x3,    g_x3);
    cudaGetSymbolAddress(&p_hlin2, g_hlin2);
    cudaGetSymbolAddress(&p_out2,  g_out2);
    cudaGetSymbolAddress(&p_xr2,   g_xr2);
    cudaGetSymbolAddress(&p_maxu,  g_maxu);
    cudaGetSymbolAddress(&p_den,   g_den);
    cudaGetSymbolAddress(&p_shat,  g_shat);
    cudaGetSymbolAddress(&p_ssum,  g_ssum);

    cudaFuncSetAttribute(f1_pool, cudaFuncAttributeMaxDynamicSharedMemorySize, 17152*4);

    // reset accumulators (memset nodes are graph-capturable)
    cudaMemsetAsync(p_maxu, 0, (size_t)NN*4*sizeof(unsigned));
    cudaMemsetAsync(p_den,  0, (size_t)NN*4*sizeof(float));
    cudaMemsetAsync(p_out1, 0, (size_t)NN*256*sizeof(float));
    cudaMemsetAsync(p_out2, 0, (size_t)NN*256*sizeof(float));
    cudaMemsetAsync(p_shat, 0, NB*64*sizeof(float));
    cudaMemsetAsync(p_ssum, 0, NB*64*sizeof(float));

    // root @ W_claim{1,2} : [128,512]@[512,64]
    sgemm128<<<dim3(1,1), 256>>>(root, W_claim1, (float*)p_rc1, NB, HID, IN_F);
    sgemm128<<<dim3(1,1), 256>>>(root, W_claim2, (float*)p_rc2, NB, HID, IN_F);
    // h_x = x @ W_post1 : [65536,512]@[512,64]
    sgemm128<<<dim3(1, NN/128), 256>>>(x, W_post1, (float*)p_hx, NN, HID, IN_F);
    // gate 1 -> h1 [N,128]
    e1_gate<<<(NN*HID + 255)/256, 256>>>(batch);
    // GAT1 lin: h1 @ W1 : [65536,128]@[128,256]
    sgemm128<<<dim3(4, NN/128), 256>>>((const float*)p_h1, W1, (float*)p_hlin1, NN, 256, 128);
    // attn scores + edge softmax + scatter
    attn_scores<<<(NN*32 + 255)/256, 256>>>((const float*)p_hlin1, att_src1, att_dst1);
    edge_max<<<(ETOT + 255)/256, 256>>>(ei);
    edge_den<<<(ETOT + 255)/256, 256>>>(ei);
    edge_scatter<<<(ETOT*32 + 255)/256, 256>>>(ei, (const float*)p_hlin1, (float*)p_out1);
    // relu(out + b1)
    e3_relu_bias<<<(NN*256 + 255)/256, 256>>>(b1);
    // hs = per-head x2r @ W_post2 : [262144,64]@[64,64]
    sgemm128<<<dim3(1, (NN*4)/128), 256>>>((const float*)p_x2r, W_post2, (float*)p_hs, NN*4, HID, HID);
    // gate 2 -> x3 [N,512]
    e4_gate2<<<(NN*256 + 255)/256, 256>>>(batch);
    // GAT2 lin: x3 @ W2 : [65536,512]@[512,256]
    sgemm128<<<dim3(4, NN/128), 256>>>((const float*)p_x3, W2, (float*)p_hlin2, NN, 256, 512);
    attn_scores<<<(NN*32 + 255)/256, 256>>>((const float*)p_hlin2, att_src2, att_dst2);
    // reset max/den for second GAT (stream-ordered after GAT1 consumed them)
    cudaMemsetAsync(p_maxu, 0, (size_t)NN*4*sizeof(unsigned));
    cudaMemsetAsync(p_den,  0, (size_t)NN*4*sizeof(float));
    edge_max<<<(ETOT + 255)/256, 256>>>(ei);
    edge_den<<<(ETOT + 255)/256, 256>>>(ei);
    edge_scatter<<<(ETOT*32 + 255)/256, 256>>>(ei, (const float*)p_hlin2, (float*)p_out2);
    // head-mean + bias + relu -> xr2 [N,64]
    e6_headmean<<<(NN*64 + 255)/256, 256>>>(b2);
    // pooling
    f1_pool<<<2048, 256, 17152*4>>>(nullptr, batch, ptr, W_fc, b_fc);
    // classifier + log_softmax
    f2_clf<<<1, 128>>>(W_clf, b_clf, out);
}

// round 2
// speedup vs baseline: 1.1155x; 1.1155x over previous
#include <cuda_runtime.h>
#include <cuda_bf16.h>
#include <math.h>
#include <stdint.h>

// ---------------- problem constants (fixed shapes) ----------------
#define NN      65536          // nodes
#define NB      128            // graphs
#define NG      512            // nodes/graph
#define NE      65536          // directed edges before flip+loops
#define ETOT    (2*NE + NN)    // 196608
#define IN_F    512
#define HID     64
#define OUTF    64
#define NHEAD   4
#define NC      4

// ---------------- scratch (device globals; no allocation) ----------------
__device__ float g_rc1[NB*HID];
__device__ float g_rc2[NB*HID];
__device__ float g_hx [(size_t)NN*HID];
__device__ float g_h1 [(size_t)NN*2*HID];
__device__ float g_hlin1[(size_t)NN*256];
__device__ float g_out1 [(size_t)NN*256];
__device__ float g_x2r  [(size_t)NN*256];
__device__ float g_hs   [(size_t)NN*256];
__device__ float g_x3   [(size_t)NN*512];
__device__ float g_hlin2[(size_t)NN*256];
__device__ float g_out2 [(size_t)NN*256];
__device__ float g_xr2  [(size_t)NN*64];
__device__ float g_asrc [(size_t)NN*4];
__device__ float g_adst [(size_t)NN*4];
__device__ unsigned g_maxu[(size_t)NN*4];
__device__ float g_den  [(size_t)NN*4];
__device__ float g_ebuf [(size_t)ETOT*4];
__device__ float g_shat [NB*64];
__device__ float g_ssum [NB*64];

// ---------------- tf32 helpers ----------------
__device__ __forceinline__ uint32_t f2tf32(float x) {
    uint32_t u;
    asm("cvt.rna.tf32.f32 %0, %1;" : "=r"(u) : "f"(x));
    return u;
}
__device__ __forceinline__ void mma_tf32(float* d,
                                         uint32_t a0, uint32_t a1, uint32_t a2, uint32_t a3,
                                         uint32_t b0, uint32_t b1) {
    asm volatile(
        "mma.sync.aligned.m16n8k8.row.col.f32.tf32.tf32.f32 "
        "{%0,%1,%2,%3},{%4,%5,%6,%7},{%8,%9},{%0,%1,%2,%3};"
        : "+f"(d[0]), "+f"(d[1]), "+f"(d[2]), "+f"(d[3])
        : "r"(a0), "r"(a1), "r"(a2), "r"(a3), "r"(b0), "r"(b1));
}

// ---------------- 3xtf32 tensor-core GEMM ----------------
// C[M,N] = A[M,K] @ B[K,N]; BM=128, BK=16; 256 threads (8 warps 4x2).
// 3-term compensation: hi*hi + lo*hi + hi*lo  (near-fp32 accuracy).
template<int BN>
__global__ __launch_bounds__(256) void gemm_tf32x3(
    const float* __restrict__ A, const float* __restrict__ B,
    float* __restrict__ C, int M, int N, int K)
{
    constexpr int BM = 128, BK = 16;
    constexpr int AST = 20;        // A smem row stride (bank-conflict-free frag loads)
    constexpr int BST = BN + 8;    // B smem row stride
    constexpr int WN  = BN / 2;    // warp n-span
    constexpr int NT  = WN / 8;    // mma n-tiles per warp

    __shared__ uint32_t sAh[BM*AST], sAl[BM*AST];
    __shared__ uint32_t sBh[BK*BST], sBl[BK*BST];

    const int tid  = threadIdx.x;
    const int lane = tid & 31;
    const int wid  = tid >> 5;
    const int wm   = wid & 3;      // 0..3
    const int wn   = wid >> 2;     // 0..1
    const int m0   = blockIdx.y * BM;
    const int n0   = blockIdx.x * BN;

    float acc[2][NT][4];
    #pragma unroll
    for (int mi = 0; mi < 2; mi++)
        #pragma unroll
        for (int ni = 0; ni < NT; ni++)
            #pragma unroll
            for (int j = 0; j < 4; j++) acc[mi][ni][j] = 0.f;

    for (int k0 = 0; k0 < K; k0 += BK) {
        // ---- A tile: 128x16 floats = 512 float4, 2 per thread ----
        #pragma unroll
        for (int t = 0; t < 2; t++) {
            int idx = tid + t*256;
            int r = idx >> 2, c4 = (idx & 3) << 2;
            float4 v = *(const float4*)(A + (size_t)(m0 + r)*K + k0 + c4);
            float vv[4] = {v.x, v.y, v.z, v.w};
            #pragma unroll
            for (int j = 0; j < 4; j++) {
                uint32_t hi = f2tf32(vv[j]);
                float hif = __uint_as_float(hi);
                sAh[r*AST + c4 + j] = hi;
                sAl[r*AST + c4 + j] = f2tf32(vv[j] - hif);
            }
        }
        // ---- B tile: 16xBN floats ----
        if (BN == 128) {
            #pragma unroll
            for (int t = 0; t < 2; t++) {
                int idx = tid + t*256;
                int r = idx >> 5, c4 = (idx & 31) << 2;
                float4 v = *(const float4*)(B + (size_t)(k0 + r)*N + n0 + c4);
                float vv[4] = {v.x, v.y, v.z, v.w};
                #pragma unroll
                for (int j = 0; j < 4; j++) {
                    uint32_t hi = f2tf32(vv[j]);
                    float hif = __uint_as_float(hi);
                    sBh[r*BST + c4 + j] = hi;
                    sBl[r*BST + c4 + j] = f2tf32(vv[j] - hif);
                }
            }
        } else { // BN == 64
            int r = tid >> 4, c4 = (tid & 15) << 2;
            float4 v = *(const float4*)(B + (size_t)(k0 + r)*N + n0 + c4);
            float vv[4] = {v.x, v.y, v.z, v.w};
            #pragma unroll
            for (int j = 0; j < 4; j++) {
                uint32_t hi = f2tf32(vv[j]);
                float hif = __uint_as_float(hi);
                sBh[r*BST + c4 + j] = hi;
                sBl[r*BST + c4 + j] = f2tf32(vv[j] - hif);
            }
        }
        __syncthreads();

        #pragma unroll
        for (int kk = 0; kk < 2; kk++) {
            const int kb = kk*8;
            uint32_t ah[2][4], al[2][4];
            #pragma unroll
            for (int mi = 0; mi < 2; mi++) {
                int row = wm*32 + mi*16 + (lane >> 2);
                int col = kb + (lane & 3);
                ah[mi][0] = sAh[row*AST + col];
                ah[mi][1] = sAh[(row+8)*AST + col];
                ah[mi][2] = sAh[row*AST + col + 4];
                ah[mi][3] = sAh[(row+8)*AST + col + 4];
                al[mi][0] = sAl[row*AST + col];
                al[mi][1] = sAl[(row+8)*AST + col];
                al[mi][2] = sAl[row*AST + col + 4];
                al[mi][3] = sAl[(row+8)*AST + col + 4];
            }
            #pragma unroll
            for (int ni = 0; ni < NT; ni++) {
                int nb = wn*WN + ni*8 + (lane >> 2);
                int kr = kb + (lane & 3);
                uint32_t bh0 = sBh[kr*BST + nb], bh1 = sBh[(kr+4)*BST + nb];
                uint32_t bl0 = sBl[kr*BST + nb], bl1 = sBl[(kr+4)*BST + nb];
                #pragma unroll
                for (int mi = 0; mi < 2; mi++) {
                    mma_tf32(acc[mi][ni], ah[mi][0], ah[mi][1], ah[mi][2], ah[mi][3], bh0, bh1);
                    mma_tf32(acc[mi][ni], al[mi][0], al[mi][1], al[mi][2], al[mi][3], bh0, bh1);
                    mma_tf32(acc[mi][ni], ah[mi][0], ah[mi][1], ah[mi][2], ah[mi][3], bl0, bl1);
                }
            }
        }
        __syncthreads();
    }

    #pragma unroll
    for (int mi = 0; mi < 2; mi++) {
        #pragma unroll
        for (int ni = 0; ni < NT; ni++) {
            int row = m0 + wm*32 + mi*16 + (lane >> 2);
            int col = n0 + wn*WN + ni*8 + (lane & 3)*2;
            *(float2*)(C + (size_t)row*N + col)     = make_float2(acc[mi][ni][0], acc[mi][ni][1]);
            *(float2*)(C + (size_t)(row+8)*N + col) = make_float2(acc[mi][ni][2], acc[mi][ni][3]);
        }
    }
}

// ---------------- small FFMA SGEMM (root GEMMs, M=128) ----------------
__global__ __launch_bounds__(256) void sgemm128(
    const float* __restrict__ A, const float* __restrict__ B,
    float* __restrict__ C, int M, int N, int K)
{
    __shared__ float As[32][128+4];
    __shared__ float Bs[32][64];
    const int tid = threadIdx.x;
    const int tx = tid & 15;
    const int ty = tid >> 4;
    const int m0 = blockIdx.y * 128;
    const int n0 = blockIdx.x * 64;
    float acc[8][4];
    #pragma unroll
    for (int i = 0; i < 8; i++)
        #pragma unroll
        for (int j = 0; j < 4; j++) acc[i][j] = 0.f;

    for (int k0 = 0; k0 < K; k0 += 32) {
        #pragma unroll
        for (int t = 0; t < 4; t++) {
            int idx = tid + t*256;
            int r = idx >> 3, c4 = (idx & 7) << 2;
            float4 v = *(const float4*)(A + (size_t)(m0 + r)*K + k0 + c4);
            As[c4+0][r] = v.x; As[c4+1][r] = v.y;
            As[c4+2][r] = v.z; As[c4+3][r] = v.w;
        }
        #pragma unroll
        for (int t = 0; t < 2; t++) {
            int idx = tid + t*256;
            int r = idx >> 4, c4 = (idx & 15) << 2;
            *(float4*)(&Bs[r][c4]) = *(const float4*)(B + (size_t)(k0 + r)*N + n0 + c4);
        }
        __syncthreads();
        #pragma unroll
        for (int k = 0; k < 32; k++) {
            float4 a0 = *(const float4*)(&As[k][ty*8]);
            float4 a1 = *(const float4*)(&As[k][ty*8+4]);
            float4 b  = *(const float4*)(&Bs[k][tx*4]);
            float av[8] = {a0.x,a0.y,a0.z,a0.w,a1.x,a1.y,a1.z,a1.w};
            float bv[4] = {b.x,b.y,b.z,b.w};
            #pragma unroll
            for (int i = 0; i < 8; i++)
                #pragma unroll
                for (int j = 0; j < 4; j++) acc[i][j] += av[i]*bv[j];
        }
        __syncthreads();
    }
    #pragma unroll
    for (int i = 0; i < 8; i++) {
        float4 v = make_float4(acc[i][0], acc[i][1], acc[i][2], acc[i][3]);
        *(float4*)(C + (size_t)(m0 + ty*8 + i)*N + n0 + tx*4) = v;
    }
}

// ---------------- elementwise / fusion kernels (float4) ----------------
__global__ void e1_gate(const int* __restrict__ batch) {
    int idx = blockIdx.x*blockDim.x + threadIdx.x;     // NN*16 threads
    if (idx >= NN*16) return;
    int n = idx >> 4, c4 = (idx & 15) << 2;
    float4 hx = *(const float4*)(g_hx + (size_t)n*64 + c4);
    float4 hc = *(const float4*)(g_rc1 + batch[n]*64 + c4);
    float4 f, s;
    float hxa[4] = {hx.x,hx.y,hx.z,hx.w}, hca[4] = {hc.x,hc.y,hc.z,hc.w};
    float fa[4];
    #pragma unroll
    for (int j = 0; j < 4; j++) {
        float g = 1.f / (1.f + __expf(-(hxa[j] + hca[j])));
        fa[j] = g*hxa[j] + (1.f - g)*hca[j];
    }
    f = make_float4(fa[0],fa[1],fa[2],fa[3]);
    s = hx;
    *(float4*)(g_h1 + (size_t)n*128 + c4)      = f;
    *(float4*)(g_h1 + (size_t)n*128 + 64 + c4) = s;
}

__global__ void e3_relu_bias(const float* __restrict__ b1) {
    int idx = blockIdx.x*blockDim.x + threadIdx.x;     // NN*64 threads
    if (idx >= NN*64) return;
    float4 v = *(const float4*)(g_out1 + (size_t)idx*4);
    float4 b = *(const float4*)(b1 + ((idx & 63) << 2));
    v.x = fmaxf(v.x + b.x, 0.f); v.y = fmaxf(v.y + b.y, 0.f);
    v.z = fmaxf(v.z + b.z, 0.f); v.w = fmaxf(v.w + b.w, 0.f);
    *(float4*)(g_x2r + (size_t)idx*4) = v;
}

__global__ void e4_gate2(const int* __restrict__ batch) {
    int idx = blockIdx.x*blockDim.x + threadIdx.x;     // NN*64 threads
    if (idx >= NN*64) return;
    int n = idx >> 6, r = idx & 63;
    int k = r >> 4, c4 = (r & 15) << 2;
    float4 hs = *(const float4*)(g_hs + (size_t)n*256 + k*64 + c4);
    float4 hc = *(const float4*)(g_rc2 + batch[n]*64 + c4);
    float hsa[4] = {hs.x,hs.y,hs.z,hs.w}, hca[4] = {hc.x,hc.y,hc.z,hc.w};
    float fa[4];
    #pragma unroll
    for (int j = 0; j < 4; j++) {
        float g = 1.f / (1.f + __expf(-(hsa[j] + hca[j])));
        fa[j] = g*hsa[j] + (1.f - g)*hca[j];
    }
    *(float4*)(g_x3 + (size_t)n*512 + k*128 + c4)      = make_float4(fa[0],fa[1],fa[2],fa[3]);
    *(float4*)(g_x3 + (size_t)n*512 + k*128 + 64 + c4) = hs;
}

__global__ void e6_headmean(const float* __restrict__ b2) {
    int idx = blockIdx.x*blockDim.x + threadIdx.x;     // NN*16 threads
    if (idx >= NN*16) return;
    int n = idx >> 4, c4 = (idx & 15) << 2;
    size_t base = (size_t)n*256;
    float4 a = *(const float4*)(g_out2 + base + c4);
    float4 b = *(const float4*)(g_out2 + base + 64 + c4);
    float4 c = *(const float4*)(g_out2 + base + 128 + c4);
    float4 d = *(const float4*)(g_out2 + base + 192 + c4);
    float4 bb = *(const float4*)(b2 + c4);
    float4 o;
    o.x = fmaxf((a.x+b.x+c.x+d.x)*0.25f + bb.x, 0.f);
    o.y = fmaxf((a.y+b.y+c.y+d.y)*0.25f + bb.y, 0.f);
    o.z = fmaxf((a.z+b.z+c.z+d.z)*0.25f + bb.z, 0.f);
    o.w = fmaxf((a.w+b.w+c.w+d.w)*0.25f + bb.w, 0.f);
    *(float4*)(g_xr2 + (size_t)n*64 + c4) = o;
}

// ---------------- attention score reduction: warp per node ----------------
__global__ void attn_scores(const float* __restrict__ h,
                            const float* __restrict__ aw_src,
                            const float* __restrict__ aw_dst) {
    int w = (int)(((size_t)blockIdx.x*blockDim.x + threadIdx.x) >> 5);
    int lane = threadIdx.x & 31;
    if (w >= NN) return;
    const float* row = h + (size_t)w*256;
    #pragma unroll
    for (int hh = 0; hh < 4; hh++) {
        float v0 = row[hh*64 + lane], v1 = row[hh*64 + 32 + lane];
        float sa = v0*aw_src[hh*64+lane] + v1*aw_src[hh*64+32+lane];
        float sd = v0*aw_dst[hh*64+lane] + v1*aw_dst[hh*64+32+lane];
        #pragma unroll
        for (int off = 16; off; off >>= 1) {
            sa += __shfl_down_sync(0xffffffffu, sa, off);
            sd += __shfl_down_sync(0xffffffffu, sd, off);
        }
        if (lane == 0) { g_asrc[w*4+hh] = sa; g_adst[w*4+hh] = sd; }
    }
}

// ---------------- edge helpers ----------------
__device__ __forceinline__ void edge_sd(const int* __restrict__ ei, int i, int& s, int& d) {
    if (i < NE)            { s = ei[i];            d = ei[NE + i]; }
    else if (i < 2*NE)     { int j = i - NE; s = ei[NE + j]; d = ei[j]; }
    else                   { s = d = i - 2*NE; }
}
__device__ __forceinline__ unsigned fenc(float f) {
    unsigned b = __float_as_uint(f);
    return (b & 0x80000000u) ? ~b : (b | 0x80000000u);
}
__device__ __forceinline__ float fdec(unsigned u) {
    return (u & 0x80000000u) ? __uint_as_float(u & 0x7FFFFFFFu) : __uint_as_float(~u);
}

__global__ void edge_max(const int* __restrict__ ei) {
    int i = blockIdx.x*blockDim.x + threadIdx.x;
    if (i >= ETOT) return;
    int s, d; edge_sd(ei, i, s, d);
    #pragma unroll
    for (int hh = 0; hh < 4; hh++) {
        float t = g_asrc[s*4+hh] + g_adst[d*4+hh];
        t = t > 0.f ? t : 0.2f*t;                   // LeakyReLU(0.2)
        g_ebuf[(size_t)i*4+hh] = t;
        atomicMax(&g_maxu[d*4+hh], fenc(t));
    }
}

__global__ void edge_den(const int* __restrict__ ei) {
    int i = blockIdx.x*blockDim.x + threadIdx.x;
    if (i >= ETOT) return;
    int s, d; edge_sd(ei, i, s, d); (void)s;
    #pragma unroll
    for (int hh = 0; hh < 4; hh++) {
        float m = fdec(g_maxu[d*4+hh]);
        float ex = expf(g_ebuf[(size_t)i*4+hh] - m);
        g_ebuf[(size_t)i*4+hh] = ex;
        atomicAdd(&g_den[d*4+hh], ex);
    }
}

// warp per edge: out[d, :256] += alpha[head] * h[s, :256]
__global__ void edge_scatter(const int* __restrict__ ei,
                             const float* __restrict__ h, float* __restrict__ out) {
    int w = (int)(((size_t)blockIdx.x*blockDim.x + threadIdx.x) >> 5);
    int lane = threadIdx.x & 31;
    if (w >= ETOT) return;
    int s, d; edge_sd(ei, w, s, d);
    float al[4];
    #pragma unroll
    for (int hh = 0; hh < 4; hh++)
        al[hh] = g_ebuf[(size_t)w*4+hh] / g_den[d*4+hh];
    const float* hr = h + (size_t)s*256;
    float* orow = out + (size_t)d*256;
    #pragma unroll
    for (int t = 0; t < 8; t++) {
        int c = t*32 + lane;
        atomicAdd(&orow[c], al[t >> 1] * hr[c]);
    }
}

// ---------------- pooling ----------------
__global__ void f1_pool(const int* __restrict__ batch,
                        const int* __restrict__ ptr,
                        const float* __restrict__ Wfc,
                        const float* __restrict__ bfc) {
    extern __shared__ float sm[];
    float* sw = sm;               // 256*64
    float* sx = sm + 16384;       // 4*64
    float* sc = sm + 16640;       // 4*64
    float* tb = sm + 16896;       // 4*64
    int tid = threadIdx.x;
    for (int i = tid; i < 16384; i += 256) sw[i] = Wfc[i];
    __syncthreads();
    int grp = tid >> 6, j = tid & 63;
    float bj = bfc[j];
    for (int base = blockIdx.x*4; base < NN; base += gridDim.x*4) {
        int n = base + grp;
        int g = batch[n];
        int rn = ptr[g];
        sx[grp*64 + j] = g_xr2[(size_t)n*64 + j];
        sc[grp*64 + j] = g_xr2[(size_t)rn*64 + j];
        __syncthreads();
        const float* px = sx + grp*64;
        const float* pc = sc + grp*64;
        float t = bj;
        #pragma unroll 8
        for (int i = 0; i < 64; i++) {
            float xv = px[i], cv = pc[i];
            t += cv*sw[i*64 + j] + xv*sw[(64+i)*64 + j]
               + (xv*cv)*sw[(128+i)*64 + j] + fabsf(cv - xv)*sw[(192+i)*64 + j];
        }
        t = tanhf(t);
        tb[tid] = t;
        __syncthreads();
        float mx = -1e30f;
        #pragma unroll 8
        for (int i = 0; i < 64; i++) mx = fmaxf(mx, tb[grp*64 + i]);
        float ex = expf(t - mx);
        __syncthreads();
        tb[tid] = ex;
        __syncthreads();
        float sum = 0.f;
        #pragma unroll 8
        for (int i = 0; i < 64; i++) sum += tb[grp*64 + i];
        float beta = ex / sum;
        float xv = px[j];
        atomicAdd(&g_shat[g*64 + j], beta * xv);
        atomicAdd(&g_ssum[g*64 + j], xv);
        __syncthreads();
    }
}

// ---------------- classifier + log_softmax ----------------
__global__ void f2_clf(const float* __restrict__ Wclf, const float* __restrict__ bclf,
                       float* __restrict__ out) {
    int g = threadIdx.x;   // 128 graphs
    float l[4];
    #pragma unroll
    for (int c = 0; c < 4; c++) l[c] = bclf[c];
    const float inv = 1.0f / (float)NG;
    for (int j = 0; j < 64; j++) {
        float a = g_shat[g*64 + j] * inv;
        float b = g_ssum[g*64 + j] * inv;
        #pragma unroll
        for (int c = 0; c < 4; c++)
            l[c] += a*Wclf[j*4 + c] + b*Wclf[(64+j)*4 + c];
    }
    float m = fmaxf(fmaxf(l[0], l[1]), fmaxf(l[2], l[3]));
    float s = 0.f;
    #pragma unroll
    for (int c = 0; c < 4; c++) s += expf(l[c] - m);
    float ls = logf(s);
    #pragma unroll
    for (int c = 0; c < 4; c++) out[g*4 + c] = l[c] - m - ls;
}

// ---------------- launch ----------------
extern "C" void kernel_launch(void* const* d_in, const int* in_sizes, int n_in,
                              void* d_out, int out_size) {
    const float* x        = (const float*)d_in[0];
    const float* root     = (const float*)d_in[1];
    const int*   ei       = (const int*)  d_in[2];
    const int*   batch    = (const int*)  d_in[3];
    const int*   ptr      = (const int*)  d_in[4];
    const float* W_post1  = (const float*)d_in[5];
    const float* W_claim1 = (const float*)d_in[6];
    const float* W1       = (const float*)d_in[7];
    const float* att_src1 = (const float*)d_in[8];
    const float* att_dst1 = (const float*)d_in[9];
    const float* b1       = (const float*)d_in[10];
    const float* W_post2  = (const float*)d_in[11];
    const float* W_claim2 = (const float*)d_in[12];
    const float* W2       = (const float*)d_in[13];
    const float* att_src2 = (const float*)d_in[14];
    const float* att_dst2 = (const float*)d_in[15];
    const float* b2       = (const float*)d_in[16];
    const float* W_fc     = (const float*)d_in[17];
    const float* b_fc     = (const float*)d_in[18];
    const float* W_clf    = (const float*)d_in[19];
    const float* b_clf    = (const float*)d_in[20];
    float* out = (float*)d_out;

    void *p_rc1, *p_rc2, *p_hx, *p_h1, *p_hlin1, *p_out1, *p_x2r, *p_hs, *p_x3,
         *p_hlin2, *p_out2, *p_maxu, *p_den, *p_shat, *p_ssum;
    cudaGetSymbolAddress(&p_rc1,   g_rc1);
    cudaGetSymbolAddress(&p_rc2,   g_rc2);
    cudaGetSymbolAddress(&p_hx,    g_hx);
    cudaGetSymbolAddress(&p_h1,    g_h1);
    cudaGetSymbolAddress(&p_hlin1, g_hlin1);
    cudaGetSymbolAddress(&p_out1,  g_out1);
    cudaGetSymbolAddress(&p_x2r,   g_x2r);
    cudaGetSymbolAddress(&p_hs,    g_hs);
    cudaGetSymbolAddress(&p_x3,    g_x3);
    cudaGetSymbolAddress(&p_hlin2, g_hlin2);
    cudaGetSymbolAddress(&p_out2,  g_out2);
    cudaGetSymbolAddress(&p_maxu,  g_maxu);
    cudaGetSymbolAddress(&p_den,   g_den);
    cudaGetSymbolAddress(&p_shat,  g_shat);
    cudaGetSymbolAddress(&p_ssum,  g_ssum);

    cudaFuncSetAttribute(f1_pool, cudaFuncAttributeMaxDynamicSharedMemorySize, 17152*4);

    // reset accumulators
    cudaMemsetAsync(p_maxu, 0, (size_t)NN*4*sizeof(unsigned));
    cudaMemsetAsync(p_den,  0, (size_t)NN*4*sizeof(float));
    cudaMemsetAsync(p_out1, 0, (size_t)NN*256*sizeof(float));
    cudaMemsetAsync(p_out2, 0, (size_t)NN*256*sizeof(float));
    cudaMemsetAsync(p_shat, 0, NB*64*sizeof(float));
    cudaMemsetAsync(p_ssum, 0, NB*64*sizeof(float));

    // root @ W_claim{1,2} : [128,512]@[512,64] (tiny, FFMA)
    sgemm128<<<dim3(1,1), 256>>>(root, W_claim1, (float*)p_rc1, NB, HID, IN_F);
    sgemm128<<<dim3(1,1), 256>>>(root, W_claim2, (float*)p_rc2, NB, HID, IN_F);
    // h_x = x @ W_post1 : [65536,512]@[512,64] -- tensor core
    gemm_tf32x3<64><<<dim3(1, NN/128), 256>>>(x, W_post1, (float*)p_hx, NN, HID, IN_F);
    // gate 1 -> h1 [N,128]
    e1_gate<<<(NN*16 + 255)/256, 256>>>(batch);
    // GAT1 lin: h1 @ W1 : [65536,128]@[128,256]
    gemm_tf32x3<128><<<dim3(2, NN/128), 256>>>((const float*)p_h1, W1, (float*)p_hlin1, NN, 256, 128);
    // attn scores + edge softmax + scatter
    attn_scores<<<(NN*32 + 255)/256, 256>>>((const float*)p_hlin1, att_src1, att_dst1);
    edge_max<<<(ETOT + 255)/256, 256>>>(ei);
    edge_den<<<(ETOT + 255)/256, 256>>>(ei);
    edge_scatter<<<(ETOT*32 + 255)/256, 256>>>(ei, (const float*)p_hlin1, (float*)p_out1);
    // relu(out + b1)
    e3_relu_bias<<<(NN*64 + 255)/256, 256>>>(b1);
    // hs = per-head x2r @ W_post2 : [262144,64]@[64,64]
    gemm_tf32x3<64><<<dim3(1, (NN*4)/128), 256>>>((const float*)p_x2r, W_post2, (float*)p_hs, NN*4, HID, HID);
    // gate 2 -> x3 [N,512]
    e4_gate2<<<(NN*64 + 255)/256, 256>>>(batch);
    // GAT2 lin: x3 @ W2 : [65536,512]@[512,256]
    gemm_tf32x3<128><<<dim3(2, NN/128), 256>>>((const float*)p_x3, W2, (float*)p_hlin2, NN, 256, 512);
    attn_scores<<<(NN*32 + 255)/256, 256>>>((const float*)p_hlin2, att_src2, att_dst2);
    // reset max/den for second GAT
    cudaMemsetAsync(p_maxu, 0, (size_t)NN*4*sizeof(unsigned));
    cudaMemsetAsync(p_den,  0, (size_t)NN*4*sizeof(float));
    edge_max<<<(ETOT + 255)/256, 256>>>(ei);
    edge_den<<<(ETOT + 255)/256, 256>>>(ei);
    edge_scatter<<<(ETOT*32 + 255)/256, 256>>>(ei, (const float*)p_hlin2, (float*)p_out2);
    // head-mean + bias + relu -> xr2 [N,64]
    e6_headmean<<<(NN*16 + 255)/256, 256>>>(b2);
    // pooling
    f1_pool<<<2048, 256, 17152*4>>>(batch, ptr, W_fc, b_fc);
    // classifier + log_softmax
    f2_clf<<<1, 128>>>(W_clf, b_clf, out);
}